// round 1
// baseline (speedup 1.0000x reference)
#include <cuda_runtime.h>
#include <cuda_bf16.h>
#include <cstdint>

// ---------------- problem constants ----------------
#define BB      2
#define LL      4096
#define DM      768
#define DIN     1536
#define NH      24
#define HD      64
#define DS      64
#define CONVD   1664          // DIN + 2*DS
#define DPROJ   3224          // 2*DIN + 2*DS + NH
#define BLROWS  (BB*LL)       // 8192
#define CHUNK   64
#define NCHUNK  (LL/CHUNK)    // 64

// ---------------- scratch (static device memory; no allocs) ----------------
__device__ float g_zx   [(size_t)BLROWS*DPROJ];        // in-proj output
__device__ float g_xbc  [(size_t)BLROWS*CONVD];        // conv+silu output
__device__ float g_dt   [(size_t)BLROWS*NH];           // softplus(dt+bias)
__device__ float g_dA   [(size_t)BLROWS*NH];           // exp(dt*A)
__device__ float g_S    [(size_t)BB*NH*NCHUNK*DS*HD];  // per-chunk end states (zero init)
__device__ float g_hini [(size_t)BB*NH*NCHUNK*DS*HD];  // per-chunk initial states
__device__ float g_P    [BB*NH*NCHUNK];                // per-chunk decay product
__device__ float g_y    [(size_t)BLROWS*DIN];          // ssm output -> gated+normed

// ---------------- fp32 tiled GEMM: C[M,N] = A[M,K] @ B[K,N], row major ------
// M multiple of 128, K multiple of 8. N arbitrary (guarded).
__global__ void __launch_bounds__(256) sgemm_k(
    const float* __restrict__ A, const float* __restrict__ Bm,
    float* __restrict__ C, int M, int N, int K)
{
    __shared__ float As[8][128];
    __shared__ float Bs[8][128];

    const int bx = blockIdx.x;         // N tile
    const int by = blockIdx.y;         // M tile
    const int tid = threadIdx.x;
    const int tr = tid / 16;           // 0..15
    const int tc = tid % 16;           // 0..15
    const int row0 = by * 128;
    const int col0 = bx * 128;

    const int aRow = tid >> 1;            // 0..127
    const int aCol = (tid & 1) * 4;       // 0 or 4
    const int bRow = tid >> 5;            // 0..7
    const int bCol = (tid & 31) * 4;      // 0..124

    float acc[8][8];
#pragma unroll
    for (int i = 0; i < 8; i++)
#pragma unroll
        for (int j = 0; j < 8; j++) acc[i][j] = 0.f;

    for (int k0 = 0; k0 < K; k0 += 8) {
        // A tile (always in-bounds: M%128==0, K%8==0)
        float4 av = *reinterpret_cast<const float4*>(&A[(size_t)(row0 + aRow) * K + k0 + aCol]);
        As[aCol + 0][aRow] = av.x;
        As[aCol + 1][aRow] = av.y;
        As[aCol + 2][aRow] = av.z;
        As[aCol + 3][aRow] = av.w;

        // B tile (guard N)
        int bc = col0 + bCol;
        float4 bv;
        if (bc + 3 < N) {
            bv = *reinterpret_cast<const float4*>(&Bm[(size_t)(k0 + bRow) * N + bc]);
        } else {
            float t0 = (bc + 0 < N) ? Bm[(size_t)(k0 + bRow) * N + bc + 0] : 0.f;
            float t1 = (bc + 1 < N) ? Bm[(size_t)(k0 + bRow) * N + bc + 1] : 0.f;
            float t2 = (bc + 2 < N) ? Bm[(size_t)(k0 + bRow) * N + bc + 2] : 0.f;
            float t3 = (bc + 3 < N) ? Bm[(size_t)(k0 + bRow) * N + bc + 3] : 0.f;
            bv = make_float4(t0, t1, t2, t3);
        }
        *reinterpret_cast<float4*>(&Bs[bRow][bCol]) = bv;

        __syncthreads();

#pragma unroll
        for (int kk = 0; kk < 8; kk++) {
            float ar[8], br[8];
#pragma unroll
            for (int i = 0; i < 8; i++) ar[i] = As[kk][tr * 8 + i];
#pragma unroll
            for (int j = 0; j < 8; j++) br[j] = Bs[kk][tc * 8 + j];
#pragma unroll
            for (int i = 0; i < 8; i++)
#pragma unroll
                for (int j = 0; j < 8; j++) acc[i][j] = fmaf(ar[i], br[j], acc[i][j]);
        }
        __syncthreads();
    }

#pragma unroll
    for (int i = 0; i < 8; i++) {
        int r = row0 + tr * 8 + i;
#pragma unroll
        for (int j = 0; j < 8; j++) {
            int c = col0 + tc * 8 + j;
            if (c < N) C[(size_t)r * N + c] = acc[i][j];
        }
    }
}

// ---------------- conv (depthwise causal, 4 taps) + silu + dt prep ----------
__global__ void __launch_bounds__(256) conv_dt_k(
    const float* __restrict__ conv_w, const float* __restrict__ conv_b,
    const float* __restrict__ dt_bias, const float* __restrict__ A_log)
{
    const int row = blockIdx.x;            // 0..BLROWS-1
    const int b = row / LL;
    const int l = row % LL;

    for (int c = threadIdx.x; c < CONVD; c += blockDim.x) {
        float acc = conv_b[c];
#pragma unroll
        for (int k = 0; k < 4; k++) {
            int ls = l - 3 + k;
            if (ls >= 0)
                acc = fmaf(g_zx[((size_t)(b * LL + ls)) * DPROJ + DIN + c], conv_w[c * 4 + k], acc);
        }
        float s = acc / (1.f + __expf(-acc));   // silu
        g_xbc[(size_t)row * CONVD + c] = s;
    }

    for (int h = threadIdx.x; h < NH; h += blockDim.x) {
        float v = g_zx[(size_t)row * DPROJ + (DIN + CONVD) + h] + dt_bias[h];
        float sp = (v > 20.f) ? v : log1pf(expf(v));     // softplus
        float Ah = -expf(A_log[h]);
        g_dt[(size_t)row * NH + h] = sp;
        g_dA[(size_t)row * NH + h] = expf(sp * Ah);
    }
}

// ---------------- scan pass 1: per-chunk end states (zero init) -------------
// 1 warp handles 32 p-values for one (b,h,chunk); 64 states/lane in registers.
__global__ void __launch_bounds__(256) scan1_k()
{
    const int w    = (blockIdx.x * blockDim.x + threadIdx.x) >> 5;
    const int lane = threadIdx.x & 31;
    const int bhc  = w >> 1;
    const int pg   = w & 1;
    const int b    = bhc / (NH * NCHUNK);
    const int rem  = bhc % (NH * NCHUNK);
    const int h    = rem / NCHUNK;
    const int c    = rem % NCHUNK;
    const int p    = pg * 32 + lane;

    float st[DS];
#pragma unroll
    for (int n = 0; n < DS; n++) st[n] = 0.f;
    float Pp = 1.f;

    const int rowbase = b * LL + c * CHUNK;
    for (int t = 0; t < CHUNK; t++) {
        const int row = rowbase + t;
        const float dA = g_dA[(size_t)row * NH + h];
        const float dt = g_dt[(size_t)row * NH + h];
        const float* xr = g_xbc + (size_t)row * CONVD;
        const float u = dt * xr[h * HD + p];
        const float Bv0 = xr[DIN + lane];
        const float Bv1 = xr[DIN + 32 + lane];
        Pp *= dA;
#pragma unroll
        for (int n = 0; n < DS; n++) {
            float bn = __shfl_sync(0xffffffffu, (n < 32) ? Bv0 : Bv1, n & 31);
            st[n] = fmaf(dA, st[n], u * bn);
        }
    }

    float* Sp = g_S + (size_t)bhc * DS * HD;
#pragma unroll
    for (int n = 0; n < DS; n++) Sp[n * HD + p] = st[n];
    if (pg == 0 && lane == 0) g_P[bhc] = Pp;
}

// ---------------- combine: sequential over chunks, parallel over states -----
__global__ void __launch_bounds__(256) combine_k()
{
    const int i = blockIdx.x * blockDim.x + threadIdx.x;
    if (i >= BB * NH * DS * HD) return;
    const int pn = i % (DS * HD);
    const int bh = i / (DS * HD);
    float hp = 0.f;
    const float* P = g_P + bh * NCHUNK;
    const size_t base = (size_t)bh * NCHUNK * DS * HD + pn;
    for (int c = 0; c < NCHUNK; c++) {
        g_hini[base + (size_t)c * DS * HD] = hp;
        hp = fmaf(hp, P[c], g_S[base + (size_t)c * DS * HD]);
    }
}

// ---------------- scan pass 2: replay with correct init, produce y ----------
__global__ void __launch_bounds__(256) scan2_k(const float* __restrict__ Dp)
{
    const int w    = (blockIdx.x * blockDim.x + threadIdx.x) >> 5;
    const int lane = threadIdx.x & 31;
    const int bhc  = w >> 1;
    const int pg   = w & 1;
    const int b    = bhc / (NH * NCHUNK);
    const int rem  = bhc % (NH * NCHUNK);
    const int h    = rem / NCHUNK;
    const int c    = rem % NCHUNK;
    const int p    = pg * 32 + lane;

    float st[DS];
    const float* hi = g_hini + (size_t)bhc * DS * HD;
#pragma unroll
    for (int n = 0; n < DS; n++) st[n] = hi[n * HD + p];

    const float Dh = Dp[h];
    const int rowbase = b * LL + c * CHUNK;
    for (int t = 0; t < CHUNK; t++) {
        const int row = rowbase + t;
        const float dA = g_dA[(size_t)row * NH + h];
        const float dt = g_dt[(size_t)row * NH + h];
        const float* xr = g_xbc + (size_t)row * CONVD;
        const float x = xr[h * HD + p];
        const float u = dt * x;
        const float Bv0 = xr[DIN + lane];
        const float Bv1 = xr[DIN + 32 + lane];
        const float Cv0 = xr[DIN + DS + lane];
        const float Cv1 = xr[DIN + DS + 32 + lane];
        float y = 0.f;
#pragma unroll
        for (int n = 0; n < DS; n++) {
            float bn = __shfl_sync(0xffffffffu, (n < 32) ? Bv0 : Bv1, n & 31);
            float cn = __shfl_sync(0xffffffffu, (n < 32) ? Cv0 : Cv1, n & 31);
            st[n] = fmaf(dA, st[n], u * bn);
            y = fmaf(st[n], cn, y);
        }
        g_y[(size_t)row * DIN + h * HD + p] = fmaf(Dh, x, y);
    }
}

// ---------------- gate (silu(z)) + RMSNorm (in place on g_y) ----------------
__global__ void __launch_bounds__(512) gatenorm_k(const float* __restrict__ norm_w)
{
    const int row = blockIdx.x;
    const float* zrow = g_zx + (size_t)row * DPROJ;
    float* yrow = g_y + (size_t)row * DIN;

    float gv[3];
    float ss = 0.f;
#pragma unroll
    for (int j = 0; j < 3; j++) {
        int i = threadIdx.x + j * 512;
        float z = zrow[i];
        float g = yrow[i] * (z / (1.f + __expf(-z)));
        gv[j] = g;
        ss = fmaf(g, g, ss);
    }

    __shared__ float red[16];
#pragma unroll
    for (int o = 16; o; o >>= 1) ss += __shfl_xor_sync(0xffffffffu, ss, o);
    if ((threadIdx.x & 31) == 0) red[threadIdx.x >> 5] = ss;
    __syncthreads();
    if (threadIdx.x < 16) {
        float v = red[threadIdx.x];
#pragma unroll
        for (int o = 8; o; o >>= 1) v += __shfl_xor_sync(0x0000ffffu, v, o);
        if (threadIdx.x == 0) red[0] = v;
    }
    __syncthreads();
    const float scale = rsqrtf(red[0] / (float)DIN + 1e-5f);
#pragma unroll
    for (int j = 0; j < 3; j++) {
        int i = threadIdx.x + j * 512;
        yrow[i] = gv[j] * scale * norm_w[i];
    }
}

// ---------------- launch ----------------------------------------------------
extern "C" void kernel_launch(void* const* d_in, const int* in_sizes, int n_in,
                              void* d_out, int out_size)
{
    const float* x       = (const float*)d_in[0];
    const float* W_in    = (const float*)d_in[1];
    const float* conv_w  = (const float*)d_in[2];
    const float* conv_b  = (const float*)d_in[3];
    const float* dt_bias = (const float*)d_in[4];
    const float* A_log   = (const float*)d_in[5];
    const float* Dp      = (const float*)d_in[6];
    const float* norm_w  = (const float*)d_in[7];
    const float* W_out   = (const float*)d_in[8];
    float* out           = (float*)d_out;

    float* zx = nullptr; float* yb = nullptr;
    cudaGetSymbolAddress((void**)&zx, g_zx);
    cudaGetSymbolAddress((void**)&yb, g_y);

    // 1) zxbcdt = x @ W_in   (8192 x 3224 x 768)
    {
        dim3 grid((DPROJ + 127) / 128, BLROWS / 128);
        sgemm_k<<<grid, 256>>>(x, W_in, zx, BLROWS, DPROJ, DM);
    }

    // 2) causal conv + silu + dt softplus / dA
    conv_dt_k<<<BLROWS, 256>>>(conv_w, conv_b, dt_bias, A_log);

    // 3) chunked scan
    {
        int total_warps = BB * NH * NCHUNK * 2;               // 6144
        scan1_k<<<total_warps * 32 / 256, 256>>>();
        int nstates = BB * NH * DS * HD;                      // 196608
        combine_k<<<(nstates + 255) / 256, 256>>>();
        scan2_k<<<total_warps * 32 / 256, 256>>>(Dp);
    }

    // 4) gate + RMSNorm (in place)
    gatenorm_k<<<BLROWS, 512>>>(norm_w);

    // 5) out = y @ W_out   (8192 x 768 x 1536)
    {
        dim3 grid((DM + 127) / 128, BLROWS / 128);
        sgemm_k<<<grid, 256>>>(yb, W_out, out, BLROWS, DM, DIN);
    }
}

// round 2
// speedup vs baseline: 2.0121x; 2.0121x over previous
#include <cuda_runtime.h>
#include <cuda_bf16.h>
#include <cstdint>

// ---------------- problem constants ----------------
#define BB      2
#define LL      4096
#define DM      768
#define DIN     1536
#define NH      24
#define HD      64
#define DS      64
#define CONVD   1664          // DIN + 2*DS
#define DPROJ   3224          // 2*DIN + 2*DS + NH
#define BLROWS  (BB*LL)       // 8192
#define CHUNK   64
#define NCHUNK  (LL/CHUNK)    // 64

// ---------------- scratch (static device memory; no allocs) ----------------
__device__ float g_zx   [(size_t)BLROWS*DPROJ];        // in-proj output (fp32)
__device__ float g_xbc  [(size_t)BLROWS*CONVD];        // conv+silu output
__device__ float g_dt   [(size_t)BLROWS*NH];
__device__ float g_dA   [(size_t)BLROWS*NH];
__device__ float g_S    [(size_t)BB*NH*NCHUNK*DS*HD];
__device__ float g_hini [(size_t)BB*NH*NCHUNK*DS*HD];
__device__ float g_P    [BB*NH*NCHUNK];
__device__ float g_y    [(size_t)BLROWS*DIN];          // ssm output (fp32)

// split-bf16 operands
__device__ __nv_bfloat16 g_xh [(size_t)BLROWS*DM];
__device__ __nv_bfloat16 g_xl [(size_t)BLROWS*DM];
__device__ __nv_bfloat16 g_wih[(size_t)DPROJ*DM];      // W_in^T  [N][K]
__device__ __nv_bfloat16 g_wil[(size_t)DPROJ*DM];
__device__ __nv_bfloat16 g_yh [(size_t)BLROWS*DIN];
__device__ __nv_bfloat16 g_yl [(size_t)BLROWS*DIN];
__device__ __nv_bfloat16 g_woh[(size_t)DM*DIN];        // W_out^T [N][K]
__device__ __nv_bfloat16 g_wol[(size_t)DM*DIN];

// ======================= split helpers =====================================
__global__ void __launch_bounds__(256) split_x_k(
    const float* __restrict__ X, __nv_bfloat16* __restrict__ Xh,
    __nv_bfloat16* __restrict__ Xl, int n4)
{
    int i = blockIdx.x * blockDim.x + threadIdx.x;
    if (i >= n4) return;
    float4 v = reinterpret_cast<const float4*>(X)[i];
    __nv_bfloat16 h0 = __float2bfloat16(v.x), h1 = __float2bfloat16(v.y);
    __nv_bfloat16 h2 = __float2bfloat16(v.z), h3 = __float2bfloat16(v.w);
    __nv_bfloat162 hh0{h0, h1}, hh1{h2, h3};
    __nv_bfloat162 ll0{__float2bfloat16(v.x - __bfloat162float(h0)),
                       __float2bfloat16(v.y - __bfloat162float(h1))};
    __nv_bfloat162 ll1{__float2bfloat16(v.z - __bfloat162float(h2)),
                       __float2bfloat16(v.w - __bfloat162float(h3))};
    reinterpret_cast<__nv_bfloat162*>(Xh)[i * 2 + 0] = hh0;
    reinterpret_cast<__nv_bfloat162*>(Xh)[i * 2 + 1] = hh1;
    reinterpret_cast<__nv_bfloat162*>(Xl)[i * 2 + 0] = ll0;
    reinterpret_cast<__nv_bfloat162*>(Xl)[i * 2 + 1] = ll1;
}

// W[K][N] -> T[N][K] split into hi/lo bf16
__global__ void __launch_bounds__(256) tsplit_k(
    const float* __restrict__ W, __nv_bfloat16* __restrict__ Th,
    __nv_bfloat16* __restrict__ Tl, int K, int N)
{
    __shared__ float tile[32][33];
    int k0 = blockIdx.x * 32, n0 = blockIdx.y * 32;
    int tx = threadIdx.x % 32, ty = threadIdx.x / 32;   // ty 0..7
#pragma unroll
    for (int i = ty; i < 32; i += 8) {
        int k = k0 + i, n = n0 + tx;
        tile[i][tx] = (k < K && n < N) ? W[(size_t)k * N + n] : 0.f;
    }
    __syncthreads();
#pragma unroll
    for (int i = ty; i < 32; i += 8) {
        int n = n0 + i, k = k0 + tx;
        if (n < N && k < K) {
            float v = tile[tx][i];
            __nv_bfloat16 h = __float2bfloat16(v);
            Th[(size_t)n * K + k] = h;
            Tl[(size_t)n * K + k] = __float2bfloat16(v - __bfloat162float(h));
        }
    }
}

// ======================= tensor-core split-bf16 GEMM ========================
// C[M,N](fp32) = Ah@Bh^T + Ah@Bl^T + Al@Bh^T ; A[M][K], B stored [N][K].
// BM=BN=128, BK=32, 256 threads (8 warps, 2x4), warp tile 64x32.
#define GSTRIDE 40                 // smem row stride in bf16 (conflict-free frags)
#define GPART   (128*GSTRIDE)      // 5120 elems per matrix-half
#define GBUF    (4*GPART)          // per pipeline buffer
#define GSMEM_BYTES (2*GBUF*2)     // 81920

__device__ __forceinline__ void cp16(uint32_t s, const void* g, bool pred) {
    int sz = pred ? 16 : 0;
    asm volatile("cp.async.cg.shared.global [%0], [%1], 16, %2;\n"
                 :: "r"(s), "l"(g), "r"(sz));
}
__device__ __forceinline__ void mma_bf16(float* d, const uint32_t* a, const uint32_t* b) {
    asm volatile("mma.sync.aligned.m16n8k16.row.col.f32.bf16.bf16.f32 "
                 "{%0,%1,%2,%3}, {%4,%5,%6,%7}, {%8,%9}, {%0,%1,%2,%3};"
                 : "+f"(d[0]), "+f"(d[1]), "+f"(d[2]), "+f"(d[3])
                 : "r"(a[0]), "r"(a[1]), "r"(a[2]), "r"(a[3]), "r"(b[0]), "r"(b[1]));
}

__global__ void __launch_bounds__(256) mma_gemm_k(
    const __nv_bfloat16* __restrict__ Ah, const __nv_bfloat16* __restrict__ Al,
    const __nv_bfloat16* __restrict__ Bh, const __nv_bfloat16* __restrict__ Bl,
    float* __restrict__ C, int Nn, int K)
{
    extern __shared__ __nv_bfloat16 sm[];
    const int tid  = threadIdx.x;
    const int lane = tid & 31;
    const int wid  = tid >> 5;
    const int wm   = wid >> 2;          // 0..1
    const int wn   = wid & 3;           // 0..3
    const int g    = lane >> 2;         // 0..7
    const int tig  = lane & 3;          // 0..3

    const int row0 = blockIdx.y * 128;
    const int col0 = blockIdx.x * 128;
    const int iters = K / 32;

    const int r0 = tid >> 2, s0 = tid & 3;   // load mapping

    float acc[4][4][4];
#pragma unroll
    for (int mi = 0; mi < 4; mi++)
#pragma unroll
        for (int ni = 0; ni < 4; ni++)
#pragma unroll
            for (int q = 0; q < 4; q++) acc[mi][ni][q] = 0.f;

    auto load_tiles = [&](int buf, int it) {
        const int k0 = it * 32;
        __nv_bfloat16* base = sm + buf * GBUF;
        uint32_t sAh = (uint32_t)__cvta_generic_to_shared(base);
        uint32_t sAl = (uint32_t)__cvta_generic_to_shared(base + GPART);
        uint32_t sBh = (uint32_t)__cvta_generic_to_shared(base + 2 * GPART);
        uint32_t sBl = (uint32_t)__cvta_generic_to_shared(base + 3 * GPART);
#pragma unroll
        for (int j = 0; j < 2; j++) {
            int r = r0 + j * 64;
            uint32_t soff = (uint32_t)(r * GSTRIDE + s0 * 8) * 2;
            size_t ga = (size_t)(row0 + r) * K + k0 + s0 * 8;
            cp16(sAh + soff, Ah + ga, true);
            cp16(sAl + soff, Al + ga, true);
            int nb = col0 + r;
            bool p = nb < Nn;
            size_t gb = (size_t)(p ? nb : 0) * K + k0 + s0 * 8;
            cp16(sBh + soff, Bh + gb, p);
            cp16(sBl + soff, Bl + gb, p);
        }
        asm volatile("cp.async.commit_group;\n" ::);
    };

    load_tiles(0, 0);

    for (int it = 0; it < iters; it++) {
        if (it + 1 < iters) {
            load_tiles((it + 1) & 1, it + 1);
            asm volatile("cp.async.wait_group 1;\n" ::);
        } else {
            asm volatile("cp.async.wait_group 0;\n" ::);
        }
        __syncthreads();

        const __nv_bfloat16* base = sm + (it & 1) * GBUF;
        const __nv_bfloat16* pAh = base;
        const __nv_bfloat16* pAl = base + GPART;
        const __nv_bfloat16* pBh = base + 2 * GPART;
        const __nv_bfloat16* pBl = base + 3 * GPART;

#pragma unroll
        for (int kk = 0; kk < 32; kk += 16) {
            uint32_t ah[4][4], al[4][4], bh[4][2], bl[4][2];
#pragma unroll
            for (int mi = 0; mi < 4; mi++) {
                int rb = wm * 64 + mi * 16;
                const __nv_bfloat16* p0 = pAh + (rb + g) * GSTRIDE + kk + 2 * tig;
                const __nv_bfloat16* p1 = pAh + (rb + g + 8) * GSTRIDE + kk + 2 * tig;
                ah[mi][0] = *(const uint32_t*)(p0);
                ah[mi][1] = *(const uint32_t*)(p1);
                ah[mi][2] = *(const uint32_t*)(p0 + 8);
                ah[mi][3] = *(const uint32_t*)(p1 + 8);
                const __nv_bfloat16* q0 = pAl + (rb + g) * GSTRIDE + kk + 2 * tig;
                const __nv_bfloat16* q1 = pAl + (rb + g + 8) * GSTRIDE + kk + 2 * tig;
                al[mi][0] = *(const uint32_t*)(q0);
                al[mi][1] = *(const uint32_t*)(q1);
                al[mi][2] = *(const uint32_t*)(q0 + 8);
                al[mi][3] = *(const uint32_t*)(q1 + 8);
            }
#pragma unroll
            for (int ni = 0; ni < 4; ni++) {
                int nb = wn * 32 + ni * 8;
                const __nv_bfloat16* p0 = pBh + (nb + g) * GSTRIDE + kk + 2 * tig;
                bh[ni][0] = *(const uint32_t*)(p0);
                bh[ni][1] = *(const uint32_t*)(p0 + 8);
                const __nv_bfloat16* q0 = pBl + (nb + g) * GSTRIDE + kk + 2 * tig;
                bl[ni][0] = *(const uint32_t*)(q0);
                bl[ni][1] = *(const uint32_t*)(q0 + 8);
            }
            // pass 1: Ah*Bh
#pragma unroll
            for (int mi = 0; mi < 4; mi++)
#pragma unroll
                for (int ni = 0; ni < 4; ni++) mma_bf16(acc[mi][ni], ah[mi], bh[ni]);
            // pass 2: Ah*Bl
#pragma unroll
            for (int mi = 0; mi < 4; mi++)
#pragma unroll
                for (int ni = 0; ni < 4; ni++) mma_bf16(acc[mi][ni], ah[mi], bl[ni]);
            // pass 3: Al*Bh
#pragma unroll
            for (int mi = 0; mi < 4; mi++)
#pragma unroll
                for (int ni = 0; ni < 4; ni++) mma_bf16(acc[mi][ni], al[mi], bh[ni]);
        }
        __syncthreads();
    }

    // epilogue
#pragma unroll
    for (int mi = 0; mi < 4; mi++) {
        int ra = row0 + wm * 64 + mi * 16 + g;
#pragma unroll
        for (int ni = 0; ni < 4; ni++) {
            int c = col0 + wn * 32 + ni * 8 + 2 * tig;
            if (c < Nn) {
                *reinterpret_cast<float2*>(&C[(size_t)ra * Nn + c]) =
                    make_float2(acc[mi][ni][0], acc[mi][ni][1]);
                *reinterpret_cast<float2*>(&C[(size_t)(ra + 8) * Nn + c]) =
                    make_float2(acc[mi][ni][2], acc[mi][ni][3]);
            }
        }
    }
}

// ---------------- conv (depthwise causal, 4 taps) + silu + dt prep ----------
__global__ void __launch_bounds__(256) conv_dt_k(
    const float* __restrict__ conv_w, const float* __restrict__ conv_b,
    const float* __restrict__ dt_bias, const float* __restrict__ A_log)
{
    const int row = blockIdx.x;
    const int b = row / LL;
    const int l = row % LL;

    for (int c = threadIdx.x; c < CONVD; c += blockDim.x) {
        float acc = conv_b[c];
#pragma unroll
        for (int k = 0; k < 4; k++) {
            int ls = l - 3 + k;
            if (ls >= 0)
                acc = fmaf(g_zx[((size_t)(b * LL + ls)) * DPROJ + DIN + c], conv_w[c * 4 + k], acc);
        }
        g_xbc[(size_t)row * CONVD + c] = acc / (1.f + __expf(-acc));
    }

    for (int h = threadIdx.x; h < NH; h += blockDim.x) {
        float v = g_zx[(size_t)row * DPROJ + (DIN + CONVD) + h] + dt_bias[h];
        float sp = (v > 20.f) ? v : log1pf(expf(v));
        float Ah = -expf(A_log[h]);
        g_dt[(size_t)row * NH + h] = sp;
        g_dA[(size_t)row * NH + h] = expf(sp * Ah);
    }
}

// ---------------- scan pass 1 ----------------------------------------------
__global__ void __launch_bounds__(256) scan1_k()
{
    const int w    = (blockIdx.x * blockDim.x + threadIdx.x) >> 5;
    const int lane = threadIdx.x & 31;
    const int bhc  = w >> 1;
    const int pg   = w & 1;
    const int b    = bhc / (NH * NCHUNK);
    const int rem  = bhc % (NH * NCHUNK);
    const int h    = rem / NCHUNK;
    const int c    = rem % NCHUNK;
    const int p    = pg * 32 + lane;

    float st[DS];
#pragma unroll
    for (int n = 0; n < DS; n++) st[n] = 0.f;
    float Pp = 1.f;

    const int rowbase = b * LL + c * CHUNK;
    for (int t = 0; t < CHUNK; t++) {
        const int row = rowbase + t;
        const float dA = g_dA[(size_t)row * NH + h];
        const float dt = g_dt[(size_t)row * NH + h];
        const float* xr = g_xbc + (size_t)row * CONVD;
        const float u = dt * xr[h * HD + p];
        const float Bv0 = xr[DIN + lane];
        const float Bv1 = xr[DIN + 32 + lane];
        Pp *= dA;
#pragma unroll
        for (int n = 0; n < DS; n++) {
            float bn = __shfl_sync(0xffffffffu, (n < 32) ? Bv0 : Bv1, n & 31);
            st[n] = fmaf(dA, st[n], u * bn);
        }
    }

    float* Sp = g_S + (size_t)bhc * DS * HD;
#pragma unroll
    for (int n = 0; n < DS; n++) Sp[n * HD + p] = st[n];
    if (pg == 0 && lane == 0) g_P[bhc] = Pp;
}

// ---------------- combine ---------------------------------------------------
__global__ void __launch_bounds__(256) combine_k()
{
    const int i = blockIdx.x * blockDim.x + threadIdx.x;
    if (i >= BB * NH * DS * HD) return;
    const int pn = i % (DS * HD);
    const int bh = i / (DS * HD);
    float hp = 0.f;
    const float* P = g_P + bh * NCHUNK;
    const size_t base = (size_t)bh * NCHUNK * DS * HD + pn;
    for (int c = 0; c < NCHUNK; c++) {
        g_hini[base + (size_t)c * DS * HD] = hp;
        hp = fmaf(hp, P[c], g_S[base + (size_t)c * DS * HD]);
    }
}

// ---------------- scan pass 2 ----------------------------------------------
__global__ void __launch_bounds__(256) scan2_k(const float* __restrict__ Dp)
{
    const int w    = (blockIdx.x * blockDim.x + threadIdx.x) >> 5;
    const int lane = threadIdx.x & 31;
    const int bhc  = w >> 1;
    const int pg   = w & 1;
    const int b    = bhc / (NH * NCHUNK);
    const int rem  = bhc % (NH * NCHUNK);
    const int h    = rem / NCHUNK;
    const int c    = rem % NCHUNK;
    const int p    = pg * 32 + lane;

    float st[DS];
    const float* hi = g_hini + (size_t)bhc * DS * HD;
#pragma unroll
    for (int n = 0; n < DS; n++) st[n] = hi[n * HD + p];

    const float Dh = Dp[h];
    const int rowbase = b * LL + c * CHUNK;
    for (int t = 0; t < CHUNK; t++) {
        const int row = rowbase + t;
        const float dA = g_dA[(size_t)row * NH + h];
        const float dt = g_dt[(size_t)row * NH + h];
        const float* xr = g_xbc + (size_t)row * CONVD;
        const float x = xr[h * HD + p];
        const float u = dt * x;
        const float Bv0 = xr[DIN + lane];
        const float Bv1 = xr[DIN + 32 + lane];
        const float Cv0 = xr[DIN + DS + lane];
        const float Cv1 = xr[DIN + DS + 32 + lane];
        float y = 0.f;
#pragma unroll
        for (int n = 0; n < DS; n++) {
            float bn = __shfl_sync(0xffffffffu, (n < 32) ? Bv0 : Bv1, n & 31);
            float cn = __shfl_sync(0xffffffffu, (n < 32) ? Cv0 : Cv1, n & 31);
            st[n] = fmaf(dA, st[n], u * bn);
            y = fmaf(st[n], cn, y);
        }
        g_y[(size_t)row * DIN + h * HD + p] = fmaf(Dh, x, y);
    }
}

// ---------------- gate + RMSNorm + split to bf16 ----------------------------
__global__ void __launch_bounds__(512) gatenorm_k(const float* __restrict__ norm_w)
{
    const int row = blockIdx.x;
    const float* zrow = g_zx + (size_t)row * DPROJ;
    const float* yrow = g_y + (size_t)row * DIN;

    float gv[3];
    float ss = 0.f;
#pragma unroll
    for (int j = 0; j < 3; j++) {
        int i = threadIdx.x + j * 512;
        float z = zrow[i];
        float gg = yrow[i] * (z / (1.f + __expf(-z)));
        gv[j] = gg;
        ss = fmaf(gg, gg, ss);
    }

    __shared__ float red[16];
#pragma unroll
    for (int o = 16; o; o >>= 1) ss += __shfl_xor_sync(0xffffffffu, ss, o);
    if ((threadIdx.x & 31) == 0) red[threadIdx.x >> 5] = ss;
    __syncthreads();
    if (threadIdx.x < 16) {
        float v = red[threadIdx.x];
#pragma unroll
        for (int o = 8; o; o >>= 1) v += __shfl_xor_sync(0x0000ffffu, v, o);
        if (threadIdx.x == 0) red[0] = v;
    }
    __syncthreads();
    const float scale = rsqrtf(red[0] / (float)DIN + 1e-5f);
#pragma unroll
    for (int j = 0; j < 3; j++) {
        int i = threadIdx.x + j * 512;
        float v = gv[j] * scale * norm_w[i];
        __nv_bfloat16 h = __float2bfloat16(v);
        g_yh[(size_t)row * DIN + i] = h;
        g_yl[(size_t)row * DIN + i] = __float2bfloat16(v - __bfloat162float(h));
    }
}

// ---------------- launch ----------------------------------------------------
extern "C" void kernel_launch(void* const* d_in, const int* in_sizes, int n_in,
                              void* d_out, int out_size)
{
    const float* x       = (const float*)d_in[0];
    const float* W_in    = (const float*)d_in[1];
    const float* conv_w  = (const float*)d_in[2];
    const float* conv_b  = (const float*)d_in[3];
    const float* dt_bias = (const float*)d_in[4];
    const float* A_log   = (const float*)d_in[5];
    const float* Dp      = (const float*)d_in[6];
    const float* norm_w  = (const float*)d_in[7];
    const float* W_out   = (const float*)d_in[8];
    float* out           = (float*)d_out;

    float* zx = nullptr;
    __nv_bfloat16 *xh, *xl, *wih, *wil, *yh, *yl, *woh, *wol;
    cudaGetSymbolAddress((void**)&zx,  g_zx);
    cudaGetSymbolAddress((void**)&xh,  g_xh);
    cudaGetSymbolAddress((void**)&xl,  g_xl);
    cudaGetSymbolAddress((void**)&wih, g_wih);
    cudaGetSymbolAddress((void**)&wil, g_wil);
    cudaGetSymbolAddress((void**)&yh,  g_yh);
    cudaGetSymbolAddress((void**)&yl,  g_yl);
    cudaGetSymbolAddress((void**)&woh, g_woh);
    cudaGetSymbolAddress((void**)&wol, g_wol);

    static bool attr_set = false;
    if (!attr_set) {
        cudaFuncSetAttribute(mma_gemm_k, cudaFuncAttributeMaxDynamicSharedMemorySize,
                             GSMEM_BYTES);
        attr_set = true;
    }

    // 0) split inputs to bf16 hi/lo
    {
        int n4 = BLROWS * DM / 4;
        split_x_k<<<(n4 + 255) / 256, 256>>>(x, xh, xl, n4);
        tsplit_k<<<dim3(DM / 32, (DPROJ + 31) / 32), 256>>>(W_in, wih, wil, DM, DPROJ);
        tsplit_k<<<dim3(DIN / 32, DM / 32), 256>>>(W_out, woh, wol, DIN, DM);
    }

    // 1) zxbcdt = x @ W_in   (8192 x 3224 x 768), tensor cores
    mma_gemm_k<<<dim3((DPROJ + 127) / 128, BLROWS / 128), 256, GSMEM_BYTES>>>(
        xh, xl, wih, wil, zx, DPROJ, DM);

    // 2) causal conv + silu + dt softplus / dA
    conv_dt_k<<<BLROWS, 256>>>(conv_w, conv_b, dt_bias, A_log);

    // 3) chunked scan
    {
        int total_warps = BB * NH * NCHUNK * 2;               // 6144
        scan1_k<<<total_warps * 32 / 256, 256>>>();
        int nstates = BB * NH * DS * HD;                      // 196608
        combine_k<<<(nstates + 255) / 256, 256>>>();
        scan2_k<<<total_warps * 32 / 256, 256>>>(Dp);
    }

    // 4) gate + RMSNorm + split
    gatenorm_k<<<BLROWS, 512>>>(norm_w);

    // 5) out = y @ W_out   (8192 x 768 x 1536), tensor cores
    mma_gemm_k<<<dim3(DM / 128, BLROWS / 128), 256, GSMEM_BYTES>>>(
        yh, yl, woh, wol, out, DM, DIN);
}

// round 6
// speedup vs baseline: 2.5302x; 1.2575x over previous
#include <cuda_runtime.h>
#include <cuda_bf16.h>
#include <cstdint>

// ---------------- problem constants ----------------
#define BB      2
#define LL      4096
#define DM      768
#define DIN     1536
#define NH      24
#define HD      64
#define DS      64
#define CONVD   1664          // DIN + 2*DS
#define DPROJ   3224          // 2*DIN + 2*DS + NH
#define BLROWS  (BB*LL)       // 8192
#define CHUNK   64
#define NCHUNK  (LL/CHUNK)    // 64
#define HG      4             // heads per scan block

// single dynamic-smem symbol for the whole TU
extern __shared__ unsigned char dynsm[];

// ---------------- scratch ----------------
__device__ float g_zx   [(size_t)BLROWS*DPROJ];
__device__ float g_xbc  [(size_t)BLROWS*CONVD];
__device__ float g_dt   [(size_t)BLROWS*NH];
__device__ float g_dA   [(size_t)BLROWS*NH];
__device__ float g_S    [(size_t)BB*NH*NCHUNK*DS*HD];
__device__ float g_hini [(size_t)BB*NH*NCHUNK*DS*HD];
__device__ float g_P    [BB*NH*NCHUNK];
__device__ float g_y    [(size_t)BLROWS*DIN];

__device__ __nv_bfloat16 g_xh [(size_t)BLROWS*DM];
__device__ __nv_bfloat16 g_xl [(size_t)BLROWS*DM];
__device__ __nv_bfloat16 g_wih[(size_t)DPROJ*DM];
__device__ __nv_bfloat16 g_wil[(size_t)DPROJ*DM];
__device__ __nv_bfloat16 g_yh [(size_t)BLROWS*DIN];
__device__ __nv_bfloat16 g_yl [(size_t)BLROWS*DIN];
__device__ __nv_bfloat16 g_woh[(size_t)DM*DIN];
__device__ __nv_bfloat16 g_wol[(size_t)DM*DIN];

// ---------------- packed f32x2 helpers ----------------
typedef unsigned long long u64t;
__device__ __forceinline__ u64t pack2(float v) {
    u64t r; asm("mov.b64 %0, {%1,%1};" : "=l"(r) : "f"(v)); return r;
}
__device__ __forceinline__ u64t fma2(u64t a, u64t b, u64t c) {
    u64t d; asm("fma.rn.f32x2 %0, %1, %2, %3;" : "=l"(d) : "l"(a), "l"(b), "l"(c)); return d;
}
__device__ __forceinline__ u64t mul2(u64t a, u64t b) {
    u64t d; asm("mul.rn.f32x2 %0, %1, %2;" : "=l"(d) : "l"(a), "l"(b)); return d;
}
__device__ __forceinline__ void unpack2(u64t v, float& lo, float& hi) {
    asm("mov.b64 {%0,%1}, %2;" : "=f"(lo), "=f"(hi) : "l"(v));
}

// ======================= split helpers =====================================
__global__ void __launch_bounds__(256) split_x_k(
    const float* __restrict__ X, __nv_bfloat16* __restrict__ Xh,
    __nv_bfloat16* __restrict__ Xl, int n4)
{
    int i = blockIdx.x * blockDim.x + threadIdx.x;
    if (i >= n4) return;
    float4 v = reinterpret_cast<const float4*>(X)[i];
    __nv_bfloat16 h0 = __float2bfloat16(v.x), h1 = __float2bfloat16(v.y);
    __nv_bfloat16 h2 = __float2bfloat16(v.z), h3 = __float2bfloat16(v.w);
    __nv_bfloat162 hh0{h0, h1}, hh1{h2, h3};
    __nv_bfloat162 ll0{__float2bfloat16(v.x - __bfloat162float(h0)),
                       __float2bfloat16(v.y - __bfloat162float(h1))};
    __nv_bfloat162 ll1{__float2bfloat16(v.z - __bfloat162float(h2)),
                       __float2bfloat16(v.w - __bfloat162float(h3))};
    reinterpret_cast<__nv_bfloat162*>(Xh)[i * 2 + 0] = hh0;
    reinterpret_cast<__nv_bfloat162*>(Xh)[i * 2 + 1] = hh1;
    reinterpret_cast<__nv_bfloat162*>(Xl)[i * 2 + 0] = ll0;
    reinterpret_cast<__nv_bfloat162*>(Xl)[i * 2 + 1] = ll1;
}

__global__ void __launch_bounds__(256) tsplit_k(
    const float* __restrict__ W, __nv_bfloat16* __restrict__ Th,
    __nv_bfloat16* __restrict__ Tl, int K, int N)
{
    __shared__ float tile[32][33];
    int k0 = blockIdx.x * 32, n0 = blockIdx.y * 32;
    int tx = threadIdx.x % 32, ty = threadIdx.x / 32;
#pragma unroll
    for (int i = ty; i < 32; i += 8) {
        int k = k0 + i, n = n0 + tx;
        tile[i][tx] = (k < K && n < N) ? W[(size_t)k * N + n] : 0.f;
    }
    __syncthreads();
#pragma unroll
    for (int i = ty; i < 32; i += 8) {
        int n = n0 + i, k = k0 + tx;
        if (n < N && k < K) {
            float v = tile[tx][i];
            __nv_bfloat16 h = __float2bfloat16(v);
            Th[(size_t)n * K + k] = h;
            Tl[(size_t)n * K + k] = __float2bfloat16(v - __bfloat162float(h));
        }
    }
}

// ======================= tensor-core split-bf16 GEMM ========================
#define GSTRIDE 40
#define GPART   (128*GSTRIDE)
#define GBUF    (4*GPART)
#define GSMEM_BYTES (2*GBUF*2)     // 81920

__device__ __forceinline__ void cp16(uint32_t s, const void* g, bool pred) {
    int sz = pred ? 16 : 0;
    asm volatile("cp.async.cg.shared.global [%0], [%1], 16, %2;\n"
                 :: "r"(s), "l"(g), "r"(sz));
}
__device__ __forceinline__ void mma_bf16(float* d, const uint32_t* a, const uint32_t* b) {
    asm volatile("mma.sync.aligned.m16n8k16.row.col.f32.bf16.bf16.f32 "
                 "{%0,%1,%2,%3}, {%4,%5,%6,%7}, {%8,%9}, {%0,%1,%2,%3};"
                 : "+f"(d[0]), "+f"(d[1]), "+f"(d[2]), "+f"(d[3])
                 : "r"(a[0]), "r"(a[1]), "r"(a[2]), "r"(a[3]), "r"(b[0]), "r"(b[1]));
}
__device__ __forceinline__ void ldsm4(uint32_t* r, uint32_t a) {
    asm volatile("ldmatrix.sync.aligned.m8n8.x4.shared.b16 {%0,%1,%2,%3}, [%4];"
                 : "=r"(r[0]), "=r"(r[1]), "=r"(r[2]), "=r"(r[3]) : "r"(a));
}

__global__ void __launch_bounds__(256) mma_gemm_k(
    const __nv_bfloat16* __restrict__ Ah, const __nv_bfloat16* __restrict__ Al,
    const __nv_bfloat16* __restrict__ Bh, const __nv_bfloat16* __restrict__ Bl,
    float* __restrict__ C, int Nn, int K)
{
    __nv_bfloat16* sm = reinterpret_cast<__nv_bfloat16*>(dynsm);
    const int tid  = threadIdx.x;
    const int lane = tid & 31;
    const int wid  = tid >> 5;
    const int wm   = wid >> 2;
    const int wn   = wid & 3;
    const int g    = lane >> 2;
    const int tig  = lane & 3;

    const int row0 = blockIdx.y * 128;
    const int col0 = blockIdx.x * 128;
    const int iters = K / 32;
    const int r0 = tid >> 2, s0 = tid & 3;

    // ldmatrix lane address components
    const int arow = (lane & 7) + ((lane >> 3) & 1) * 8;
    const int acol = ((lane >> 4) & 1) * 8;
    const int brow = (lane & 7) + ((lane >> 4) & 1) * 8;
    const int bcol = ((lane >> 3) & 1) * 8;

    const uint32_t smbase = (uint32_t)__cvta_generic_to_shared(sm);
    uint32_t aoff[4], boff[2];
#pragma unroll
    for (int mi = 0; mi < 4; mi++)
        aoff[mi] = (uint32_t)(((wm * 64 + mi * 16 + arow) * GSTRIDE + acol) * 2);
#pragma unroll
    for (int nj = 0; nj < 2; nj++)
        boff[nj] = (uint32_t)(((wn * 32 + nj * 16 + brow) * GSTRIDE + bcol) * 2);

    float acc[4][4][4];
#pragma unroll
    for (int mi = 0; mi < 4; mi++)
#pragma unroll
        for (int ni = 0; ni < 4; ni++)
#pragma unroll
            for (int q = 0; q < 4; q++) acc[mi][ni][q] = 0.f;

    auto load_tiles = [&](int buf, int it) {
        const int k0 = it * 32;
        uint32_t b = smbase + buf * (GBUF * 2);
#pragma unroll
        for (int j = 0; j < 2; j++) {
            int r = r0 + j * 64;
            uint32_t soff = (uint32_t)(r * GSTRIDE + s0 * 8) * 2;
            size_t ga = (size_t)(row0 + r) * K + k0 + s0 * 8;
            cp16(b + soff, Ah + ga, true);
            cp16(b + GPART * 2 + soff, Al + ga, true);
            int nb = col0 + r;
            bool p = nb < Nn;
            size_t gb = (size_t)(p ? nb : 0) * K + k0 + s0 * 8;
            cp16(b + 2 * GPART * 2 + soff, Bh + gb, p);
            cp16(b + 3 * GPART * 2 + soff, Bl + gb, p);
        }
        asm volatile("cp.async.commit_group;\n" ::);
    };

    load_tiles(0, 0);

    for (int it = 0; it < iters; it++) {
        if (it + 1 < iters) {
            load_tiles((it + 1) & 1, it + 1);
            asm volatile("cp.async.wait_group 1;\n" ::);
        } else {
            asm volatile("cp.async.wait_group 0;\n" ::);
        }
        __syncthreads();

        uint32_t bA  = smbase + (it & 1) * (GBUF * 2);
        uint32_t bAl = bA + GPART * 2;
        uint32_t bBh = bA + 2 * GPART * 2;
        uint32_t bBl = bA + 3 * GPART * 2;

#pragma unroll
        for (int kk = 0; kk < 2; kk++) {
            const uint32_t kof = kk * 32;   // 16 bf16 = 32 bytes
            uint32_t ah[4][4], al[4][4], bh[2][4], bl[2][4];
#pragma unroll
            for (int mi = 0; mi < 4; mi++) ldsm4(ah[mi], bA + aoff[mi] + kof);
#pragma unroll
            for (int mi = 0; mi < 4; mi++) ldsm4(al[mi], bAl + aoff[mi] + kof);
#pragma unroll
            for (int nj = 0; nj < 2; nj++) ldsm4(bh[nj], bBh + boff[nj] + kof);
#pragma unroll
            for (int nj = 0; nj < 2; nj++) ldsm4(bl[nj], bBl + boff[nj] + kof);

#pragma unroll
            for (int mi = 0; mi < 4; mi++)
#pragma unroll
                for (int ni = 0; ni < 4; ni++)
                    mma_bf16(acc[mi][ni], ah[mi], &bh[ni >> 1][(ni & 1) * 2]);
#pragma unroll
            for (int mi = 0; mi < 4; mi++)
#pragma unroll
                for (int ni = 0; ni < 4; ni++)
                    mma_bf16(acc[mi][ni], ah[mi], &bl[ni >> 1][(ni & 1) * 2]);
#pragma unroll
            for (int mi = 0; mi < 4; mi++)
#pragma unroll
                for (int ni = 0; ni < 4; ni++)
                    mma_bf16(acc[mi][ni], al[mi], &bh[ni >> 1][(ni & 1) * 2]);
        }
        __syncthreads();
    }

#pragma unroll
    for (int mi = 0; mi < 4; mi++) {
        int ra = row0 + wm * 64 + mi * 16 + g;
#pragma unroll
        for (int ni = 0; ni < 4; ni++) {
            int c = col0 + wn * 32 + ni * 8 + 2 * tig;
            if (c < Nn) {
                *reinterpret_cast<float2*>(&C[(size_t)ra * Nn + c]) =
                    make_float2(acc[mi][ni][0], acc[mi][ni][1]);
                *reinterpret_cast<float2*>(&C[(size_t)(ra + 8) * Nn + c]) =
                    make_float2(acc[mi][ni][2], acc[mi][ni][3]);
            }
        }
    }
}

// ---------------- conv: smem-tiled depthwise causal conv + silu -------------
__global__ void __launch_bounds__(256) conv_k(
    const float* __restrict__ conv_w, const float* __restrict__ conv_b)
{
    __shared__ float st[35][128];
    const int c0 = blockIdx.x * 128;
    const int b  = blockIdx.y >> 7;           // /128
    const int lg = blockIdx.y & 127;
    const int l0 = lg * 32;

    for (int i = threadIdx.x; i < 35 * 128; i += 256) {
        int r = i >> 7, cc = i & 127;
        int ls = l0 - 3 + r;
        st[r][cc] = (ls >= 0) ? g_zx[(size_t)(b * LL + ls) * DPROJ + DIN + c0 + cc] : 0.f;
    }
    __syncthreads();

    for (int i = threadIdx.x; i < 32 * 128; i += 256) {
        int r = i >> 7, cc = i & 127;
        int c = c0 + cc;
        float w0 = conv_w[c * 4 + 0], w1 = conv_w[c * 4 + 1];
        float w2 = conv_w[c * 4 + 2], w3 = conv_w[c * 4 + 3];
        float acc = conv_b[c];
        acc = fmaf(st[r + 0][cc], w0, acc);
        acc = fmaf(st[r + 1][cc], w1, acc);
        acc = fmaf(st[r + 2][cc], w2, acc);
        acc = fmaf(st[r + 3][cc], w3, acc);
        g_xbc[(size_t)(b * LL + l0 + r) * CONVD + c] = acc / (1.f + __expf(-acc));
    }
}

// ---------------- dt prep ----------------------------------------------------
__global__ void __launch_bounds__(256) dt_k(
    const float* __restrict__ dt_bias, const float* __restrict__ A_log)
{
    int i = blockIdx.x * blockDim.x + threadIdx.x;
    if (i >= BLROWS * NH) return;
    int row = i / NH, h = i % NH;
    float v = g_zx[(size_t)row * DPROJ + (DIN + CONVD) + h] + dt_bias[h];
    float sp = (v > 20.f) ? v : log1pf(expf(v));
    float Ah = -expf(A_log[h]);
    g_dt[i] = sp;
    g_dA[i] = expf(sp * Ah);
}

// ---------------- scan smem layout (floats) ----------------------------------
// sB: [64][64] @0, sC: [64][64] @4096, sdA: [HG][64] @8192, sdt @8448, sx: [HG][64][64] @8704
#define SC_B   0
#define SC_C   4096
#define SC_DA  8192
#define SC_DT  8448
#define SC_X   8704
#define SCAN_SMEM_FLOATS (8704 + HG*64*64)
#define SCAN_SMEM_BYTES  (SCAN_SMEM_FLOATS*4)    // 100352

__device__ __forceinline__ void scan_stage(float* sm, int b, int c, int hg, bool withC)
{
    const int tid = threadIdx.x;
    const int rowbase = b * LL + c * CHUNK;
    // B (and C)
    for (int i = tid; i < 64 * 16; i += 256) {
        int t = i >> 4, q = i & 15;
        const float* xr = g_xbc + (size_t)(rowbase + t) * CONVD;
        *reinterpret_cast<float4*>(sm + SC_B + t * 64 + q * 4) =
            *reinterpret_cast<const float4*>(xr + DIN + q * 4);
        if (withC)
            *reinterpret_cast<float4*>(sm + SC_C + t * 64 + q * 4) =
                *reinterpret_cast<const float4*>(xr + DIN + DS + q * 4);
    }
    // dA, dt
    for (int i = tid; i < HG * 64; i += 256) {
        int hl = i >> 6, t = i & 63;
        int row = rowbase + t;
        sm[SC_DA + i] = g_dA[(size_t)row * NH + hg * HG + hl];
        sm[SC_DT + i] = g_dt[(size_t)row * NH + hg * HG + hl];
    }
    // x: sx[hl][t][p]
    for (int i = tid; i < HG * 64 * 16; i += 256) {
        int hl = i >> 10, rem = i & 1023, t = rem >> 4, q = rem & 15;
        const float* xr = g_xbc + (size_t)(rowbase + t) * CONVD;
        *reinterpret_cast<float4*>(sm + SC_X + hl * 4096 + t * 64 + q * 4) =
            *reinterpret_cast<const float4*>(xr + (hg * HG + hl) * HD + q * 4);
    }
}

// ---------------- scan pass 1 -----------------------------------------------
__global__ void __launch_bounds__(256) scan1_k()
{
    float* sm = reinterpret_cast<float*>(dynsm);
    const int bx = blockIdx.x;
    const int c  = bx % NCHUNK;
    const int r2 = bx / NCHUNK;
    const int b  = r2 / (NH / HG);
    const int hg = r2 % (NH / HG);

    scan_stage(sm, b, c, hg, false);
    __syncthreads();

    const int wid  = threadIdx.x >> 5;
    const int lane = threadIdx.x & 31;
    const int hl   = wid >> 1;
    const int pg   = wid & 1;
    const int p    = pg * 32 + lane;
    const int h    = hg * HG + hl;

    u64t st[32];
#pragma unroll
    for (int n = 0; n < 32; n++) st[n] = 0ull;
    float Pp = 1.f;

    const float* sxp = sm + SC_X + hl * 4096 + p;
    const float* sdA = sm + SC_DA + hl * 64;
    const float* sdt = sm + SC_DT + hl * 64;

    for (int t = 0; t < CHUNK; t++) {
        float dAv = sdA[t];
        float u = sdt[t] * sxp[t * 64];
        Pp *= dAv;
        u64t dA2 = pack2(dAv), u2 = pack2(u);
        const ulonglong2* B2 = reinterpret_cast<const ulonglong2*>(sm + SC_B + t * 64);
#pragma unroll
        for (int n4 = 0; n4 < 16; n4++) {
            ulonglong2 bb = B2[n4];
            st[2 * n4 + 0] = fma2(dA2, st[2 * n4 + 0], mul2(u2, bb.x));
            st[2 * n4 + 1] = fma2(dA2, st[2 * n4 + 1], mul2(u2, bb.y));
        }
    }

    const int bhc = (b * NH + h) * NCHUNK + c;
    float* Sp = g_S + (size_t)bhc * DS * HD;
#pragma unroll
    for (int n2 = 0; n2 < 32; n2++) {
        float lo, hi; unpack2(st[n2], lo, hi);
        Sp[(2 * n2 + 0) * HD + p] = lo;
        Sp[(2 * n2 + 1) * HD + p] = hi;
    }
    if (pg == 0 && lane == 0) g_P[bhc] = Pp;
}

// ---------------- combine ----------------------------------------------------
__global__ void __launch_bounds__(256) combine_k()
{
    const int i = blockIdx.x * blockDim.x + threadIdx.x;
    if (i >= BB * NH * DS * HD) return;
    const int pn = i % (DS * HD);
    const int bh = i / (DS * HD);
    float hp = 0.f;
    const float* P = g_P + bh * NCHUNK;
    const size_t base = (size_t)bh * NCHUNK * DS * HD + pn;
    for (int c = 0; c < NCHUNK; c++) {
        g_hini[base + (size_t)c * DS * HD] = hp;
        hp = fmaf(hp, P[c], g_S[base + (size_t)c * DS * HD]);
    }
}

// ---------------- scan pass 2 -----------------------------------------------
__global__ void __launch_bounds__(256) scan2_k(const float* __restrict__ Dp)
{
    float* sm = reinterpret_cast<float*>(dynsm);
    const int bx = blockIdx.x;
    const int c  = bx % NCHUNK;
    const int r2 = bx / NCHUNK;
    const int b  = r2 / (NH / HG);
    const int hg = r2 % (NH / HG);

    scan_stage(sm, b, c, hg, true);
    __syncthreads();

    const int wid  = threadIdx.x >> 5;
    const int lane = threadIdx.x & 31;
    const int hl   = wid >> 1;
    const int pg   = wid & 1;
    const int p    = pg * 32 + lane;
    const int h    = hg * HG + hl;
    const int bhc  = (b * NH + h) * NCHUNK + c;

    u64t st[32];
    const float* hiv = g_hini + (size_t)bhc * DS * HD;
#pragma unroll
    for (int n2 = 0; n2 < 32; n2++) {
        float lo = hiv[(2 * n2 + 0) * HD + p];
        float hi = hiv[(2 * n2 + 1) * HD + p];
        u64t v; asm("mov.b64 %0, {%1,%2};" : "=l"(v) : "f"(lo), "f"(hi));
        st[n2] = v;
    }

    const float Dh = Dp[h];
    const float* sxp = sm + SC_X + hl * 4096 + p;
    const float* sdA = sm + SC_DA + hl * 64;
    const float* sdt = sm + SC_DT + hl * 64;
    const int rowbase = b * LL + c * CHUNK;

    for (int t = 0; t < CHUNK; t++) {
        float dAv = sdA[t];
        float x = sxp[t * 64];
        float u = sdt[t] * x;
        u64t dA2 = pack2(dAv), u2 = pack2(u);
        u64t y2 = 0ull;
        const ulonglong2* B2 = reinterpret_cast<const ulonglong2*>(sm + SC_B + t * 64);
        const ulonglong2* C2 = reinterpret_cast<const ulonglong2*>(sm + SC_C + t * 64);
#pragma unroll
        for (int n4 = 0; n4 < 16; n4++) {
            ulonglong2 bb = B2[n4];
            ulonglong2 cc = C2[n4];
            st[2 * n4 + 0] = fma2(dA2, st[2 * n4 + 0], mul2(u2, bb.x));
            st[2 * n4 + 1] = fma2(dA2, st[2 * n4 + 1], mul2(u2, bb.y));
            y2 = fma2(st[2 * n4 + 0], cc.x, y2);
            y2 = fma2(st[2 * n4 + 1], cc.y, y2);
        }
        float ylo, yhi; unpack2(y2, ylo, yhi);
        g_y[(size_t)(rowbase + t) * DIN + h * HD + p] = fmaf(Dh, x, ylo + yhi);
    }
}

// ---------------- gate + RMSNorm + split to bf16 ----------------------------
__global__ void __launch_bounds__(512) gatenorm_k(const float* __restrict__ norm_w)
{
    const int row = blockIdx.x;
    const float* zrow = g_zx + (size_t)row * DPROJ;
    const float* yrow = g_y + (size_t)row * DIN;

    float gv[3];
    float ss = 0.f;
#pragma unroll
    for (int j = 0; j < 3; j++) {
        int i = threadIdx.x + j * 512;
        float z = zrow[i];
        float gg = yrow[i] * (z / (1.f + __expf(-z)));
        gv[j] = gg;
        ss = fmaf(gg, gg, ss);
    }

    __shared__ float red[16];
#pragma unroll
    for (int o = 16; o; o >>= 1) ss += __shfl_xor_sync(0xffffffffu, ss, o);
    if ((threadIdx.x & 31) == 0) red[threadIdx.x >> 5] = ss;
    __syncthreads();
    if (threadIdx.x < 16) {
        float v = red[threadIdx.x];
#pragma unroll
        for (int o = 8; o; o >>= 1) v += __shfl_xor_sync(0x0000ffffu, v, o);
        if (threadIdx.x == 0) red[0] = v;
    }
    __syncthreads();
    const float scale = rsqrtf(red[0] / (float)DIN + 1e-5f);
#pragma unroll
    for (int j = 0; j < 3; j++) {
        int i = threadIdx.x + j * 512;
        float v = gv[j] * scale * norm_w[i];
        __nv_bfloat16 h = __float2bfloat16(v);
        g_yh[(size_t)row * DIN + i] = h;
        g_yl[(size_t)row * DIN + i] = __float2bfloat16(v - __bfloat162float(h));
    }
}

// ---------------- launch ----------------------------------------------------
extern "C" void kernel_launch(void* const* d_in, const int* in_sizes, int n_in,
                              void* d_out, int out_size)
{
    const float* x       = (const float*)d_in[0];
    const float* W_in    = (const float*)d_in[1];
    const float* conv_w  = (const float*)d_in[2];
    const float* conv_b  = (const float*)d_in[3];
    const float* dt_bias = (const float*)d_in[4];
    const float* A_log   = (const float*)d_in[5];
    const float* Dp      = (const float*)d_in[6];
    const float* norm_w  = (const float*)d_in[7];
    const float* W_out   = (const float*)d_in[8];
    float* out           = (float*)d_out;

    float* zx = nullptr;
    __nv_bfloat16 *xh, *xl, *wih, *wil, *yh, *yl, *woh, *wol;
    cudaGetSymbolAddress((void**)&zx,  g_zx);
    cudaGetSymbolAddress((void**)&xh,  g_xh);
    cudaGetSymbolAddress((void**)&xl,  g_xl);
    cudaGetSymbolAddress((void**)&wih, g_wih);
    cudaGetSymbolAddress((void**)&wil, g_wil);
    cudaGetSymbolAddress((void**)&yh,  g_yh);
    cudaGetSymbolAddress((void**)&yl,  g_yl);
    cudaGetSymbolAddress((void**)&woh, g_woh);
    cudaGetSymbolAddress((void**)&wol, g_wol);

    static bool attr_set = false;
    if (!attr_set) {
        cudaFuncSetAttribute(mma_gemm_k, cudaFuncAttributeMaxDynamicSharedMemorySize,
                             GSMEM_BYTES);
        cudaFuncSetAttribute(scan1_k, cudaFuncAttributeMaxDynamicSharedMemorySize,
                             SCAN_SMEM_BYTES);
        cudaFuncSetAttribute(scan2_k, cudaFuncAttributeMaxDynamicSharedMemorySize,
                             SCAN_SMEM_BYTES);
        attr_set = true;
    }

    // 0) split inputs
    {
        int n4 = BLROWS * DM / 4;
        split_x_k<<<(n4 + 255) / 256, 256>>>(x, xh, xl, n4);
        tsplit_k<<<dim3(DM / 32, (DPROJ + 31) / 32), 256>>>(W_in, wih, wil, DM, DPROJ);
        tsplit_k<<<dim3(DIN / 32, DM / 32), 256>>>(W_out, woh, wol, DIN, DM);
    }

    // 1) zxbcdt = x @ W_in
    mma_gemm_k<<<dim3((DPROJ + 127) / 128, BLROWS / 128), 256, GSMEM_BYTES>>>(
        xh, xl, wih, wil, zx, DPROJ, DM);

    // 2) conv + silu ; dt prep
    conv_k<<<dim3(CONVD / 128, BB * (LL / 32)), 256>>>(conv_w, conv_b);
    dt_k<<<(BLROWS * NH + 255) / 256, 256>>>(dt_bias, A_log);

    // 3) chunked scan
    {
        int blocks = BB * (NH / HG) * NCHUNK;   // 768
        scan1_k<<<blocks, 256, SCAN_SMEM_BYTES>>>();
        int nstates = BB * NH * DS * HD;
        combine_k<<<(nstates + 255) / 256, 256>>>();
        scan2_k<<<blocks, 256, SCAN_SMEM_BYTES>>>(Dp);
    }

    // 4) gate + RMSNorm + split
    gatenorm_k<<<BLROWS, 512>>>(norm_w);

    // 5) out = y @ W_out
    mma_gemm_k<<<dim3(DM / 128, BLROWS / 128), 256, GSMEM_BYTES>>>(
        yh, yl, woh, wol, out, DM, DIN);
}

// round 8
// speedup vs baseline: 2.5688x; 1.0152x over previous
#include <cuda_runtime.h>
#include <cuda_bf16.h>
#include <cstdint>

// ---------------- problem constants ----------------
#define BB      2
#define LL      4096
#define DM      768
#define DIN     1536
#define NH      24
#define HD      64
#define DS      64
#define CONVD   1664          // DIN + 2*DS
#define DPROJ   3224          // 2*DIN + 2*DS + NH
#define BLROWS  (BB*LL)       // 8192
#define CHUNK   64
#define NCHUNK  (LL/CHUNK)    // 64
#define HG      4             // heads per scan block

// single dynamic-smem symbol for the whole TU
extern __shared__ unsigned char dynsm[];

// ---------------- scratch ----------------
__device__ float g_zx   [(size_t)BLROWS*DPROJ];
__device__ float g_xbc  [(size_t)BLROWS*CONVD];
__device__ float g_dt   [(size_t)BLROWS*NH];
__device__ float g_dA   [(size_t)BLROWS*NH];
__device__ float g_S    [(size_t)BB*NH*NCHUNK*DS*HD];
__device__ float g_hini [(size_t)BB*NH*NCHUNK*DS*HD];
__device__ float g_P    [BB*NH*NCHUNK];
__device__ float g_y    [(size_t)BLROWS*DIN];

__device__ __nv_bfloat16 g_xh [(size_t)BLROWS*DM];
__device__ __nv_bfloat16 g_xl [(size_t)BLROWS*DM];
__device__ __nv_bfloat16 g_wih[(size_t)DPROJ*DM];
__device__ __nv_bfloat16 g_wil[(size_t)DPROJ*DM];
__device__ __nv_bfloat16 g_yh [(size_t)BLROWS*DIN];
__device__ __nv_bfloat16 g_yl [(size_t)BLROWS*DIN];
__device__ __nv_bfloat16 g_woh[(size_t)DM*DIN];
__device__ __nv_bfloat16 g_wol[(size_t)DM*DIN];

// ---------------- packed f32x2 helpers ----------------
typedef unsigned long long u64t;
__device__ __forceinline__ u64t pack2(float v) {
    u64t r; asm("mov.b64 %0, {%1,%1};" : "=l"(r) : "f"(v)); return r;
}
__device__ __forceinline__ u64t fma2(u64t a, u64t b, u64t c) {
    u64t d; asm("fma.rn.f32x2 %0, %1, %2, %3;" : "=l"(d) : "l"(a), "l"(b), "l"(c)); return d;
}
__device__ __forceinline__ u64t mul2(u64t a, u64t b) {
    u64t d; asm("mul.rn.f32x2 %0, %1, %2;" : "=l"(d) : "l"(a), "l"(b)); return d;
}
__device__ __forceinline__ void unpack2(u64t v, float& lo, float& hi) {
    asm("mov.b64 {%0,%1}, %2;" : "=f"(lo), "=f"(hi) : "l"(v));
}

// ======================= split helpers =====================================
__global__ void __launch_bounds__(256) split_x_k(
    const float* __restrict__ X, __nv_bfloat16* __restrict__ Xh,
    __nv_bfloat16* __restrict__ Xl, int n4)
{
    int i = blockIdx.x * blockDim.x + threadIdx.x;
    if (i >= n4) return;
    float4 v = reinterpret_cast<const float4*>(X)[i];
    __nv_bfloat16 h0 = __float2bfloat16(v.x), h1 = __float2bfloat16(v.y);
    __nv_bfloat16 h2 = __float2bfloat16(v.z), h3 = __float2bfloat16(v.w);
    __nv_bfloat162 hh0{h0, h1}, hh1{h2, h3};
    __nv_bfloat162 ll0{__float2bfloat16(v.x - __bfloat162float(h0)),
                       __float2bfloat16(v.y - __bfloat162float(h1))};
    __nv_bfloat162 ll1{__float2bfloat16(v.z - __bfloat162float(h2)),
                       __float2bfloat16(v.w - __bfloat162float(h3))};
    reinterpret_cast<__nv_bfloat162*>(Xh)[i * 2 + 0] = hh0;
    reinterpret_cast<__nv_bfloat162*>(Xh)[i * 2 + 1] = hh1;
    reinterpret_cast<__nv_bfloat162*>(Xl)[i * 2 + 0] = ll0;
    reinterpret_cast<__nv_bfloat162*>(Xl)[i * 2 + 1] = ll1;
}

__global__ void __launch_bounds__(256) tsplit_k(
    const float* __restrict__ W, __nv_bfloat16* __restrict__ Th,
    __nv_bfloat16* __restrict__ Tl, int K, int N)
{
    __shared__ float tile[32][33];
    int k0 = blockIdx.x * 32, n0 = blockIdx.y * 32;
    int tx = threadIdx.x % 32, ty = threadIdx.x / 32;
#pragma unroll
    for (int i = ty; i < 32; i += 8) {
        int k = k0 + i, n = n0 + tx;
        tile[i][tx] = (k < K && n < N) ? W[(size_t)k * N + n] : 0.f;
    }
    __syncthreads();
#pragma unroll
    for (int i = ty; i < 32; i += 8) {
        int n = n0 + i, k = k0 + tx;
        if (n < N && k < K) {
            float v = tile[tx][i];
            __nv_bfloat16 h = __float2bfloat16(v);
            Th[(size_t)n * K + k] = h;
            Tl[(size_t)n * K + k] = __float2bfloat16(v - __bfloat162float(h));
        }
    }
}

// ======================= tensor-core split-bf16 GEMM ========================
// C[M,N](fp32) = Ah@Bh^T + Ah@Bl^T + Al@Bh^T ; A[M][K], B stored [N][K].
// 128x128 CTA tile, BK=32, 4-stage cp.async pipeline, 1 barrier per iter.
#define GSTRIDE 40
#define GPART   (128*GSTRIDE)
#define GBUF    (4*GPART)
#define NSTAGE  4
#define GSTAGE_BYTES (GBUF*2)                 // 40960
#define GSMEM_BYTES  (NSTAGE*GSTAGE_BYTES)    // 163840

__device__ __forceinline__ void cp16(uint32_t s, const void* g, bool pred) {
    int sz = pred ? 16 : 0;
    asm volatile("cp.async.cg.shared.global [%0], [%1], 16, %2;\n"
                 :: "r"(s), "l"(g), "r"(sz));
}
__device__ __forceinline__ void mma_bf16(float* d, const uint32_t* a, const uint32_t* b) {
    asm volatile("mma.sync.aligned.m16n8k16.row.col.f32.bf16.bf16.f32 "
                 "{%0,%1,%2,%3}, {%4,%5,%6,%7}, {%8,%9}, {%0,%1,%2,%3};"
                 : "+f"(d[0]), "+f"(d[1]), "+f"(d[2]), "+f"(d[3])
                 : "r"(a[0]), "r"(a[1]), "r"(a[2]), "r"(a[3]), "r"(b[0]), "r"(b[1]));
}
__device__ __forceinline__ void ldsm4(uint32_t* r, uint32_t a) {
    asm volatile("ldmatrix.sync.aligned.m8n8.x4.shared.b16 {%0,%1,%2,%3}, [%4];"
                 : "=r"(r[0]), "=r"(r[1]), "=r"(r[2]), "=r"(r[3]) : "r"(a));
}

__global__ void __launch_bounds__(256) mma_gemm_k(
    const __nv_bfloat16* __restrict__ Ah, const __nv_bfloat16* __restrict__ Al,
    const __nv_bfloat16* __restrict__ Bh, const __nv_bfloat16* __restrict__ Bl,
    float* __restrict__ C, int Nn, int K)
{
    __nv_bfloat16* sm = reinterpret_cast<__nv_bfloat16*>(dynsm);
    const int tid  = threadIdx.x;
    const int lane = tid & 31;
    const int wid  = tid >> 5;
    const int wm   = wid >> 2;
    const int wn   = wid & 3;
    const int g    = lane >> 2;
    const int tig  = lane & 3;

    const int row0 = blockIdx.y * 128;
    const int col0 = blockIdx.x * 128;
    const int iters = K / 32;
    const int r0 = tid >> 2, s0 = tid & 3;

    // ldmatrix lane address components
    const int arow = (lane & 7) + ((lane >> 3) & 1) * 8;
    const int acol = ((lane >> 4) & 1) * 8;
    const int brow = (lane & 7) + ((lane >> 4) & 1) * 8;
    const int bcol = ((lane >> 3) & 1) * 8;

    const uint32_t smbase = (uint32_t)__cvta_generic_to_shared(sm);
    uint32_t aoff[4], boff[2];
#pragma unroll
    for (int mi = 0; mi < 4; mi++)
        aoff[mi] = (uint32_t)(((wm * 64 + mi * 16 + arow) * GSTRIDE + acol) * 2);
#pragma unroll
    for (int nj = 0; nj < 2; nj++)
        boff[nj] = (uint32_t)(((wn * 32 + nj * 16 + brow) * GSTRIDE + bcol) * 2);

    float acc[4][4][4];
#pragma unroll
    for (int mi = 0; mi < 4; mi++)
#pragma unroll
        for (int ni = 0; ni < 4; ni++)
#pragma unroll
            for (int q = 0; q < 4; q++) acc[mi][ni][q] = 0.f;

    auto load_tiles = [&](int buf, int it) {
        const int k0 = it * 32;
        uint32_t b = smbase + buf * GSTAGE_BYTES;
#pragma unroll
        for (int j = 0; j < 2; j++) {
            int r = r0 + j * 64;
            uint32_t soff = (uint32_t)(r * GSTRIDE + s0 * 8) * 2;
            size_t ga = (size_t)(row0 + r) * K + k0 + s0 * 8;
            cp16(b + soff, Ah + ga, true);
            cp16(b + GPART * 2 + soff, Al + ga, true);
            int nb = col0 + r;
            bool p = nb < Nn;
            size_t gb = (size_t)(p ? nb : 0) * K + k0 + s0 * 8;
            cp16(b + 2 * GPART * 2 + soff, Bh + gb, p);
            cp16(b + 3 * GPART * 2 + soff, Bl + gb, p);
        }
        asm volatile("cp.async.commit_group;\n" ::);
    };

    // prologue: fill 3 stages (iters >= 24 for both GEMMs)
    load_tiles(0, 0);
    load_tiles(1, 1);
    load_tiles(2, 2);

    for (int it = 0; it < iters; it++) {
        asm volatile("cp.async.wait_group 2;\n" ::);
        __syncthreads();

        const int buf = it & (NSTAGE - 1);
        uint32_t bA  = smbase + buf * GSTAGE_BYTES;
        uint32_t bAl = bA + GPART * 2;
        uint32_t bBh = bA + 2 * GPART * 2;
        uint32_t bBl = bA + 3 * GPART * 2;

#pragma unroll
        for (int kk = 0; kk < 2; kk++) {
            const uint32_t kof = kk * 32;   // 16 bf16 = 32 bytes
            uint32_t ah[4][4], al[4][4], bh[2][4], bl[2][4];
#pragma unroll
            for (int mi = 0; mi < 4; mi++) ldsm4(ah[mi], bA + aoff[mi] + kof);
#pragma unroll
            for (int mi = 0; mi < 4; mi++) ldsm4(al[mi], bAl + aoff[mi] + kof);
#pragma unroll
            for (int nj = 0; nj < 2; nj++) ldsm4(bh[nj], bBh + boff[nj] + kof);
#pragma unroll
            for (int nj = 0; nj < 2; nj++) ldsm4(bl[nj], bBl + boff[nj] + kof);

#pragma unroll
            for (int mi = 0; mi < 4; mi++)
#pragma unroll
                for (int ni = 0; ni < 4; ni++)
                    mma_bf16(acc[mi][ni], ah[mi], &bh[ni >> 1][(ni & 1) * 2]);
#pragma unroll
            for (int mi = 0; mi < 4; mi++)
#pragma unroll
                for (int ni = 0; ni < 4; ni++)
                    mma_bf16(acc[mi][ni], ah[mi], &bl[ni >> 1][(ni & 1) * 2]);
#pragma unroll
            for (int mi = 0; mi < 4; mi++)
#pragma unroll
                for (int ni = 0; ni < 4; ni++)
                    mma_bf16(acc[mi][ni], al[mi], &bh[ni >> 1][(ni & 1) * 2]);
        }

        const int nx = it + 3;
        if (nx < iters) {
            load_tiles(nx & (NSTAGE - 1), nx);
        } else {
            asm volatile("cp.async.commit_group;\n" ::);   // keep group count uniform
        }
    }

#pragma unroll
    for (int mi = 0; mi < 4; mi++) {
        int ra = row0 + wm * 64 + mi * 16 + g;
#pragma unroll
        for (int ni = 0; ni < 4; ni++) {
            int c = col0 + wn * 32 + ni * 8 + 2 * tig;
            if (c < Nn) {
                *reinterpret_cast<float2*>(&C[(size_t)ra * Nn + c]) =
                    make_float2(acc[mi][ni][0], acc[mi][ni][1]);
                *reinterpret_cast<float2*>(&C[(size_t)(ra + 8) * Nn + c]) =
                    make_float2(acc[mi][ni][2], acc[mi][ni][3]);
            }
        }
    }
}

// ---------------- conv: smem-tiled depthwise causal conv + silu -------------
__global__ void __launch_bounds__(256) conv_k(
    const float* __restrict__ conv_w, const float* __restrict__ conv_b)
{
    __shared__ float st[35][128];
    const int c0 = blockIdx.x * 128;
    const int b  = blockIdx.y >> 7;           // /128
    const int lg = blockIdx.y & 127;
    const int l0 = lg * 32;

    for (int i = threadIdx.x; i < 35 * 128; i += 256) {
        int r = i >> 7, cc = i & 127;
        int ls = l0 - 3 + r;
        st[r][cc] = (ls >= 0) ? g_zx[(size_t)(b * LL + ls) * DPROJ + DIN + c0 + cc] : 0.f;
    }
    __syncthreads();

    for (int i = threadIdx.x; i < 32 * 128; i += 256) {
        int r = i >> 7, cc = i & 127;
        int c = c0 + cc;
        float w0 = conv_w[c * 4 + 0], w1 = conv_w[c * 4 + 1];
        float w2 = conv_w[c * 4 + 2], w3 = conv_w[c * 4 + 3];
        float acc = conv_b[c];
        acc = fmaf(st[r + 0][cc], w0, acc);
        acc = fmaf(st[r + 1][cc], w1, acc);
        acc = fmaf(st[r + 2][cc], w2, acc);
        acc = fmaf(st[r + 3][cc], w3, acc);
        g_xbc[(size_t)(b * LL + l0 + r) * CONVD + c] = acc / (1.f + __expf(-acc));
    }
}

// ---------------- dt prep ----------------------------------------------------
__global__ void __launch_bounds__(256) dt_k(
    const float* __restrict__ dt_bias, const float* __restrict__ A_log)
{
    int i = blockIdx.x * blockDim.x + threadIdx.x;
    if (i >= BLROWS * NH) return;
    int row = i / NH, h = i % NH;
    float v = g_zx[(size_t)row * DPROJ + (DIN + CONVD) + h] + dt_bias[h];
    float sp = (v > 20.f) ? v : log1pf(expf(v));
    float Ah = -expf(A_log[h]);
    g_dt[i] = sp;
    g_dA[i] = expf(sp * Ah);
}

// ---------------- scan smem layout (floats) ----------------------------------
#define SC_B   0
#define SC_C   4096
#define SC_DA  8192
#define SC_DT  8448
#define SC_X   8704
#define SCAN_SMEM_FLOATS (8704 + HG*64*64)
#define SCAN_SMEM_BYTES  (SCAN_SMEM_FLOATS*4)    // 100352

__device__ __forceinline__ void scan_stage(float* sm, int b, int c, int hg, bool withC)
{
    const int tid = threadIdx.x;
    const int rowbase = b * LL + c * CHUNK;
    for (int i = tid; i < 64 * 16; i += 256) {
        int t = i >> 4, q = i & 15;
        const float* xr = g_xbc + (size_t)(rowbase + t) * CONVD;
        *reinterpret_cast<float4*>(sm + SC_B + t * 64 + q * 4) =
            *reinterpret_cast<const float4*>(xr + DIN + q * 4);
        if (withC)
            *reinterpret_cast<float4*>(sm + SC_C + t * 64 + q * 4) =
                *reinterpret_cast<const float4*>(xr + DIN + DS + q * 4);
    }
    for (int i = tid; i < HG * 64; i += 256) {
        int hl = i >> 6, t = i & 63;
        int row = rowbase + t;
        sm[SC_DA + i] = g_dA[(size_t)row * NH + hg * HG + hl];
        sm[SC_DT + i] = g_dt[(size_t)row * NH + hg * HG + hl];
    }
    for (int i = tid; i < HG * 64 * 16; i += 256) {
        int hl = i >> 10, rem = i & 1023, t = rem >> 4, q = rem & 15;
        const float* xr = g_xbc + (size_t)(rowbase + t) * CONVD;
        *reinterpret_cast<float4*>(sm + SC_X + hl * 4096 + t * 64 + q * 4) =
            *reinterpret_cast<const float4*>(xr + (hg * HG + hl) * HD + q * 4);
    }
}

// ---------------- scan pass 1 -----------------------------------------------
__global__ void __launch_bounds__(256) scan1_k()
{
    float* sm = reinterpret_cast<float*>(dynsm);
    const int bx = blockIdx.x;
    const int c  = bx % NCHUNK;
    const int r2 = bx / NCHUNK;
    const int b  = r2 / (NH / HG);
    const int hg = r2 % (NH / HG);

    scan_stage(sm, b, c, hg, false);
    __syncthreads();

    const int wid  = threadIdx.x >> 5;
    const int lane = threadIdx.x & 31;
    const int hl   = wid >> 1;
    const int pg   = wid & 1;
    const int p    = pg * 32 + lane;
    const int h    = hg * HG + hl;

    u64t st[32];
#pragma unroll
    for (int n = 0; n < 32; n++) st[n] = 0ull;
    float Pp = 1.f;

    const float* sxp = sm + SC_X + hl * 4096 + p;
    const float* sdA = sm + SC_DA + hl * 64;
    const float* sdt = sm + SC_DT + hl * 64;

    for (int t = 0; t < CHUNK; t++) {
        float dAv = sdA[t];
        float u = sdt[t] * sxp[t * 64];
        Pp *= dAv;
        u64t dA2 = pack2(dAv), u2 = pack2(u);
        const ulonglong2* B2 = reinterpret_cast<const ulonglong2*>(sm + SC_B + t * 64);
#pragma unroll
        for (int n4 = 0; n4 < 16; n4++) {
            ulonglong2 bb = B2[n4];
            st[2 * n4 + 0] = fma2(dA2, st[2 * n4 + 0], mul2(u2, bb.x));
            st[2 * n4 + 1] = fma2(dA2, st[2 * n4 + 1], mul2(u2, bb.y));
        }
    }

    const int bhc = (b * NH + h) * NCHUNK + c;
    float* Sp = g_S + (size_t)bhc * DS * HD;
#pragma unroll
    for (int n2 = 0; n2 < 32; n2++) {
        float lo, hi; unpack2(st[n2], lo, hi);
        Sp[(2 * n2 + 0) * HD + p] = lo;
        Sp[(2 * n2 + 1) * HD + p] = hi;
    }
    if (pg == 0 && lane == 0) g_P[bhc] = Pp;
}

// ---------------- combine ----------------------------------------------------
__global__ void __launch_bounds__(256) combine_k()
{
    const int i = blockIdx.x * blockDim.x + threadIdx.x;
    if (i >= BB * NH * DS * HD) return;
    const int pn = i % (DS * HD);
    const int bh = i / (DS * HD);
    float hp = 0.f;
    const float* P = g_P + bh * NCHUNK;
    const size_t base = (size_t)bh * NCHUNK * DS * HD + pn;
    for (int c = 0; c < NCHUNK; c++) {
        g_hini[base + (size_t)c * DS * HD] = hp;
        hp = fmaf(hp, P[c], g_S[base + (size_t)c * DS * HD]);
    }
}

// ---------------- scan pass 2 -----------------------------------------------
__global__ void __launch_bounds__(256) scan2_k(const float* __restrict__ Dp)
{
    float* sm = reinterpret_cast<float*>(dynsm);
    const int bx = blockIdx.x;
    const int c  = bx % NCHUNK;
    const int r2 = bx / NCHUNK;
    const int b  = r2 / (NH / HG);
    const int hg = r2 % (NH / HG);

    scan_stage(sm, b, c, hg, true);
    __syncthreads();

    const int wid  = threadIdx.x >> 5;
    const int lane = threadIdx.x & 31;
    const int hl   = wid >> 1;
    const int pg   = wid & 1;
    const int p    = pg * 32 + lane;
    const int h    = hg * HG + hl;
    const int bhc  = (b * NH + h) * NCHUNK + c;

    u64t st[32];
    const float* hiv = g_hini + (size_t)bhc * DS * HD;
#pragma unroll
    for (int n2 = 0; n2 < 32; n2++) {
        float lo = hiv[(2 * n2 + 0) * HD + p];
        float hi = hiv[(2 * n2 + 1) * HD + p];
        u64t v; asm("mov.b64 %0, {%1,%2};" : "=l"(v) : "f"(lo), "f"(hi));
        st[n2] = v;
    }

    const float Dh = Dp[h];
    const float* sxp = sm + SC_X + hl * 4096 + p;
    const float* sdA = sm + SC_DA + hl * 64;
    const float* sdt = sm + SC_DT + hl * 64;
    const int rowbase = b * LL + c * CHUNK;

    for (int t = 0; t < CHUNK; t++) {
        float dAv = sdA[t];
        float x = sxp[t * 64];
        float u = sdt[t] * x;
        u64t dA2 = pack2(dAv), u2 = pack2(u);
        u64t y2 = 0ull;
        const ulonglong2* B2 = reinterpret_cast<const ulonglong2*>(sm + SC_B + t * 64);
        const ulonglong2* C2 = reinterpret_cast<const ulonglong2*>(sm + SC_C + t * 64);
#pragma unroll
        for (int n4 = 0; n4 < 16; n4++) {
            ulonglong2 bb = B2[n4];
            ulonglong2 cc = C2[n4];
            st[2 * n4 + 0] = fma2(dA2, st[2 * n4 + 0], mul2(u2, bb.x));
            st[2 * n4 + 1] = fma2(dA2, st[2 * n4 + 1], mul2(u2, bb.y));
            y2 = fma2(st[2 * n4 + 0], cc.x, y2);
            y2 = fma2(st[2 * n4 + 1], cc.y, y2);
        }
        float ylo, yhi; unpack2(y2, ylo, yhi);
        g_y[(size_t)(rowbase + t) * DIN + h * HD + p] = fmaf(Dh, x, ylo + yhi);
    }
}

// ---------------- gate + RMSNorm + split to bf16 ----------------------------
__global__ void __launch_bounds__(512) gatenorm_k(const float* __restrict__ norm_w)
{
    const int row = blockIdx.x;
    const float* zrow = g_zx + (size_t)row * DPROJ;
    const float* yrow = g_y + (size_t)row * DIN;

    float gv[3];
    float ss = 0.f;
#pragma unroll
    for (int j = 0; j < 3; j++) {
        int i = threadIdx.x + j * 512;
        float z = zrow[i];
        float gg = yrow[i] * (z / (1.f + __expf(-z)));
        gv[j] = gg;
        ss = fmaf(gg, gg, ss);
    }

    __shared__ float red[16];
#pragma unroll
    for (int o = 16; o; o >>= 1) ss += __shfl_xor_sync(0xffffffffu, ss, o);
    if ((threadIdx.x & 31) == 0) red[threadIdx.x >> 5] = ss;
    __syncthreads();
    if (threadIdx.x < 16) {
        float v = red[threadIdx.x];
#pragma unroll
        for (int o = 8; o; o >>= 1) v += __shfl_xor_sync(0x0000ffffu, v, o);
        if (threadIdx.x == 0) red[0] = v;
    }
    __syncthreads();
    const float scale = rsqrtf(red[0] / (float)DIN + 1e-5f);
#pragma unroll
    for (int j = 0; j < 3; j++) {
        int i = threadIdx.x + j * 512;
        float v = gv[j] * scale * norm_w[i];
        __nv_bfloat16 h = __float2bfloat16(v);
        g_yh[(size_t)row * DIN + i] = h;
        g_yl[(size_t)row * DIN + i] = __float2bfloat16(v - __bfloat162float(h));
    }
}

// ---------------- launch ----------------------------------------------------
extern "C" void kernel_launch(void* const* d_in, const int* in_sizes, int n_in,
                              void* d_out, int out_size)
{
    const float* x       = (const float*)d_in[0];
    const float* W_in    = (const float*)d_in[1];
    const float* conv_w  = (const float*)d_in[2];
    const float* conv_b  = (const float*)d_in[3];
    const float* dt_bias = (const float*)d_in[4];
    const float* A_log   = (const float*)d_in[5];
    const float* Dp      = (const float*)d_in[6];
    const float* norm_w  = (const float*)d_in[7];
    const float* W_out   = (const float*)d_in[8];
    float* out           = (float*)d_out;

    float* zx = nullptr;
    __nv_bfloat16 *xh, *xl, *wih, *wil, *yh, *yl, *woh, *wol;
    cudaGetSymbolAddress((void**)&zx,  g_zx);
    cudaGetSymbolAddress((void**)&xh,  g_xh);
    cudaGetSymbolAddress((void**)&xl,  g_xl);
    cudaGetSymbolAddress((void**)&wih, g_wih);
    cudaGetSymbolAddress((void**)&wil, g_wil);
    cudaGetSymbolAddress((void**)&yh,  g_yh);
    cudaGetSymbolAddress((void**)&yl,  g_yl);
    cudaGetSymbolAddress((void**)&woh, g_woh);
    cudaGetSymbolAddress((void**)&wol, g_wol);

    static bool attr_set = false;
    if (!attr_set) {
        cudaFuncSetAttribute(mma_gemm_k, cudaFuncAttributeMaxDynamicSharedMemorySize,
                             GSMEM_BYTES);
        cudaFuncSetAttribute(scan1_k, cudaFuncAttributeMaxDynamicSharedMemorySize,
                             SCAN_SMEM_BYTES);
        cudaFuncSetAttribute(scan2_k, cudaFuncAttributeMaxDynamicSharedMemorySize,
                             SCAN_SMEM_BYTES);
        attr_set = true;
    }

    // 0) split inputs
    {
        int n4 = BLROWS * DM / 4;
        split_x_k<<<(n4 + 255) / 256, 256>>>(x, xh, xl, n4);
        tsplit_k<<<dim3(DM / 32, (DPROJ + 31) / 32), 256>>>(W_in, wih, wil, DM, DPROJ);
        tsplit_k<<<dim3(DIN / 32, DM / 32), 256>>>(W_out, woh, wol, DIN, DM);
    }

    // 1) zxbcdt = x @ W_in
    mma_gemm_k<<<dim3((DPROJ + 127) / 128, BLROWS / 128), 256, GSMEM_BYTES>>>(
        xh, xl, wih, wil, zx, DPROJ, DM);

    // 2) conv + silu ; dt prep
    conv_k<<<dim3(CONVD / 128, BB * (LL / 32)), 256>>>(conv_w, conv_b);
    dt_k<<<(BLROWS * NH + 255) / 256, 256>>>(dt_bias, A_log);

    // 3) chunked scan
    {
        int blocks = BB * (NH / HG) * NCHUNK;   // 768
        scan1_k<<<blocks, 256, SCAN_SMEM_BYTES>>>();
        int nstates = BB * NH * DS * HD;
        combine_k<<<(nstates + 255) / 256, 256>>>();
        scan2_k<<<blocks, 256, SCAN_SMEM_BYTES>>>(Dp);
    }

    // 4) gate + RMSNorm + split
    gatenorm_k<<<BLROWS, 512>>>(norm_w);

    // 5) out = y @ W_out
    mma_gemm_k<<<dim3(DM / 128, BLROWS / 128), 256, GSMEM_BYTES>>>(
        yh, yl, woh, wol, out, DM, DIN);
}